// round 4
// baseline (speedup 1.0000x reference)
#include <cuda_runtime.h>
#include <cuda_bf16.h>

// Problem constants (B=2, S=2048, NX=1024, H=16, D=64)
#define BB 2
#define SS 2048
#define NX 1024
#define HH 16
#define DD 64
#define MTOK (BB*SS)   // 4096

// Scratch (device globals — no allocation allowed)
__device__ float g_q[(size_t)BB*HH*SS*DD];   // [B,H,S,D] 16 MB
__device__ float g_k[(size_t)BB*HH*SS*DD];
__device__ float g_v[(size_t)BB*HH*SS*DD];
__device__ float g_a[(size_t)BB*SS*NX];      // merged-head attn out, 16 MB

// ---------------------------------------------------------------------------
// Generic 128x128x16 SGEMM, 256 threads, 8x8 micro-tile. Static 16KB smem.
// mode 0: C[row*N+col] = acc + bias[col]
// mode 1: scatter into g_q/g_k/g_v with [B,H,S,D] layout (QKV epilogue)
// A==nullptr means "use g_a" (projection input).
// ---------------------------------------------------------------------------
__global__ __launch_bounds__(256, 2)
void sgemm_kernel(const float* __restrict__ A, const float* __restrict__ Bm,
                  const float* __restrict__ bias, float* __restrict__ C,
                  int M, int N, int K, int mode)
{
    __shared__ float As[16][128];
    __shared__ float Bs[16][128];

    const int tid = threadIdx.x;
    const int tr = tid >> 4;        // 0..15
    const int tc = tid & 15;        // 0..15
    const int row0 = blockIdx.y * 128;
    const int col0 = blockIdx.x * 128;

    const float* Ap = A ? A : g_a;

    float acc[8][8];
#pragma unroll
    for (int i = 0; i < 8; i++)
#pragma unroll
        for (int j = 0; j < 8; j++) acc[i][j] = 0.f;

    for (int k0 = 0; k0 < K; k0 += 16) {
        // Load A tile (128 rows x 16 cols), transposed into As[k][m]
#pragma unroll
        for (int t = 0; t < 2; t++) {
            int fid = tid + t * 256;           // 512 float4s
            int ar = fid >> 2;                 // 0..127
            int ac = (fid & 3) << 2;           // 0,4,8,12
            float4 v = *(const float4*)(Ap + (size_t)(row0 + ar) * K + k0 + ac);
            As[ac + 0][ar] = v.x; As[ac + 1][ar] = v.y;
            As[ac + 2][ar] = v.z; As[ac + 3][ar] = v.w;
        }
        // Load B tile (16 rows x 128 cols), natural layout
#pragma unroll
        for (int t = 0; t < 2; t++) {
            int fid = tid + t * 256;
            int br = fid >> 5;                 // 0..15
            int bc = (fid & 31) << 2;          // 0..124
            *(float4*)&Bs[br][bc] =
                *(const float4*)(Bm + (size_t)(k0 + br) * N + col0 + bc);
        }
        __syncthreads();

#pragma unroll
        for (int kk = 0; kk < 16; kk++) {
            float a[8], b[8];
            *(float4*)&a[0] = *(float4*)&As[kk][tr * 8];
            *(float4*)&a[4] = *(float4*)&As[kk][tr * 8 + 4];
            *(float4*)&b[0] = *(float4*)&Bs[kk][tc * 8];
            *(float4*)&b[4] = *(float4*)&Bs[kk][tc * 8 + 4];
#pragma unroll
            for (int i = 0; i < 8; i++)
#pragma unroll
                for (int j = 0; j < 8; j++)
                    acc[i][j] = fmaf(a[i], b[j], acc[i][j]);
        }
        __syncthreads();
    }

    // Epilogue
    if (mode == 0) {
#pragma unroll
        for (int i = 0; i < 8; i++) {
            int row = row0 + tr * 8 + i;
#pragma unroll
            for (int j = 0; j < 8; j++) {
                int col = col0 + tc * 8 + j;
                C[(size_t)row * N + col] = acc[i][j] + bias[col];
            }
        }
    } else {
#pragma unroll
        for (int i = 0; i < 8; i++) {
            int row = row0 + tr * 8 + i;
            int bidx = row >> 11;      // /2048
            int s    = row & 2047;
#pragma unroll
            for (int j = 0; j < 8; j++) {
                int col = col0 + tc * 8 + j;
                float val = acc[i][j] + bias[col];
                int which = col >> 10;     // 0:q 1:k 2:v
                int hd = col & 1023;
                int h = hd >> 6;
                int d = hd & 63;
                size_t idx = (((size_t)(bidx * HH + h)) * SS + s) * DD + d;
                if (which == 0)      g_q[idx] = val;
                else if (which == 1) g_k[idx] = val;
                else                 g_v[idx] = val;
            }
        }
    }
}

// ---------------------------------------------------------------------------
// Flash attention: one block = one (b,h) x 64-query tile. 256 threads,
// 16x16 thread grid with 4x4 micro-tiles for both 64x64x64 GEMMs.
// Static 48KB smem: Qt + one shared KV buffer (used for K^T then V) + Ps.
// Online softmax; strictly-above-diagonal KV tiles skipped (bit-equivalent:
// masked entries get -1e4 additive in the reference -> exp underflows to 0).
// ---------------------------------------------------------------------------
__global__ __launch_bounds__(256, 2)
void attn_kernel()
{
    __shared__ float Qt[64 * 64];   // [d][r]
    __shared__ float KV[64 * 64];   // K as [d][c], then V as [c][d]
    __shared__ float Ps[64 * 64];   // [c][r]

    const int bh = blockIdx.x;        // 0..31  (b*16+h)
    const int qt = blockIdx.y;        // 0..31
    const int q0 = qt * 64;
    const int tid = threadIdx.x;
    const int tr = tid >> 4;          // 0..15 -> rows tr*4..+3
    const int tc = tid & 15;          // 0..15 -> cols tc*4..+3

    const float* Qg = g_q + (size_t)bh * SS * DD;
    const float* Kg = g_k + (size_t)bh * SS * DD;
    const float* Vg = g_v + (size_t)bh * SS * DD;

    // Load Q tile transposed: Qt[d][r]
#pragma unroll
    for (int t = 0; t < 4; t++) {
        int fid = tid + t * 256;          // 1024 float4s
        int r  = fid >> 4;                // 0..63
        int c4 = (fid & 15) << 2;         // 0..60
        float4 v = *(const float4*)(Qg + (size_t)(q0 + r) * DD + c4);
        Qt[(c4 + 0) * 64 + r] = v.x; Qt[(c4 + 1) * 64 + r] = v.y;
        Qt[(c4 + 2) * 64 + r] = v.z; Qt[(c4 + 3) * 64 + r] = v.w;
    }

    float m[4], l[4], o[4][4];
#pragma unroll
    for (int i = 0; i < 4; i++) {
        m[i] = -1e30f; l[i] = 0.f;
#pragma unroll
        for (int j = 0; j < 4; j++) o[i][j] = 0.f;
    }
    const float scale = 0.125f;   // 1/sqrt(64)

    for (int kt = 0; kt <= qt; kt++) {
        const int k0 = kt * 64;

        // Barrier: KV free (prev PV done) / Qt ready on first iter
        __syncthreads();
        // Load K tile transposed: KV[d][c]
#pragma unroll
        for (int t = 0; t < 4; t++) {
            int fid = tid + t * 256;
            int r  = fid >> 4;
            int c4 = (fid & 15) << 2;
            float4 kv = *(const float4*)(Kg + (size_t)(k0 + r) * DD + c4);
            KV[(c4 + 0) * 64 + r] = kv.x; KV[(c4 + 1) * 64 + r] = kv.y;
            KV[(c4 + 2) * 64 + r] = kv.z; KV[(c4 + 3) * 64 + r] = kv.w;
        }
        __syncthreads();

        // S = Q K^T  (64x64x64)
        float s[4][4];
#pragma unroll
        for (int i = 0; i < 4; i++)
#pragma unroll
            for (int j = 0; j < 4; j++) s[i][j] = 0.f;
        for (int d = 0; d < 64; d++) {
            float4 a = *(float4*)&Qt[d * 64 + tr * 4];
            float4 b = *(float4*)&KV[d * 64 + tc * 4];
            float av[4] = {a.x, a.y, a.z, a.w};
            float bv[4] = {b.x, b.y, b.z, b.w};
#pragma unroll
            for (int i = 0; i < 4; i++)
#pragma unroll
                for (int j = 0; j < 4; j++)
                    s[i][j] = fmaf(av[i], bv[j], s[i][j]);
        }

        // scale + causal mask (only on diagonal tile)
        const bool diag = (kt == qt);
#pragma unroll
        for (int i = 0; i < 4; i++)
#pragma unroll
            for (int j = 0; j < 4; j++) {
                s[i][j] *= scale;
                if (diag && (k0 + tc * 4 + j) > (q0 + tr * 4 + i))
                    s[i][j] = -1e30f;
            }

        // online softmax update. Row i lives on the 16 threads sharing tr;
        // those are lanes (tr&1)*16 + tc within a warp, so xor-shfl over
        // offsets 8,4,2,1 reduces exactly across them.
        float alpha[4];
#pragma unroll
        for (int i = 0; i < 4; i++) {
            float mt = fmaxf(fmaxf(s[i][0], s[i][1]), fmaxf(s[i][2], s[i][3]));
#pragma unroll
            for (int off = 8; off > 0; off >>= 1)
                mt = fmaxf(mt, __shfl_xor_sync(0xffffffffu, mt, off));
            float mn = fmaxf(m[i], mt);
            alpha[i] = __expf(m[i] - mn);
            m[i] = mn;
            float sum = 0.f;
#pragma unroll
            for (int j = 0; j < 4; j++) {
                float p = __expf(s[i][j] - mn);
                s[i][j] = p;
                sum += p;
            }
#pragma unroll
            for (int off = 8; off > 0; off >>= 1)
                sum += __shfl_xor_sync(0xffffffffu, sum, off);
            l[i] = l[i] * alpha[i] + sum;
#pragma unroll
            for (int j = 0; j < 4; j++) o[i][j] *= alpha[i];
        }

        // stash P transposed: Ps[c][r]
#pragma unroll
        for (int j = 0; j < 4; j++)
            *(float4*)&Ps[(tc * 4 + j) * 64 + tr * 4] =
                make_float4(s[0][j], s[1][j], s[2][j], s[3][j]);
        // Barrier: all S reads of KV done, Ps visible -> safe to overwrite KV
        __syncthreads();

        // Load V tile natural: KV[c][d]
#pragma unroll
        for (int t = 0; t < 4; t++) {
            int fid = tid + t * 256;
            int r  = fid >> 4;
            int c4 = (fid & 15) << 2;
            *(float4*)&KV[r * 64 + c4] =
                *(const float4*)(Vg + (size_t)(k0 + r) * DD + c4);
        }
        __syncthreads();

        // O += P V  (64x64x64)
        for (int c = 0; c < 64; c++) {
            float4 a = *(float4*)&Ps[c * 64 + tr * 4];
            float4 b = *(float4*)&KV[c * 64 + tc * 4];
            float av[4] = {a.x, a.y, a.z, a.w};
            float bv[4] = {b.x, b.y, b.z, b.w};
#pragma unroll
            for (int i = 0; i < 4; i++)
#pragma unroll
                for (int j = 0; j < 4; j++)
                    o[i][j] = fmaf(av[i], bv[j], o[i][j]);
        }
    }

    // normalize + write merged-head output g_a[b][s][h*64+d]
    const int b = bh >> 4;
    const int h = bh & 15;
#pragma unroll
    for (int i = 0; i < 4; i++) {
        float inv = 1.f / l[i];
        int srow = q0 + tr * 4 + i;
        float* dst = g_a + ((size_t)(b * SS + srow)) * NX + h * DD + tc * 4;
        dst[0] = o[i][0] * inv;
        dst[1] = o[i][1] * inv;
        dst[2] = o[i][2] * inv;
        dst[3] = o[i][3] * inv;
    }
}

// ---------------------------------------------------------------------------
extern "C" void kernel_launch(void* const* d_in, const int* in_sizes, int n_in,
                              void* d_out, int out_size)
{
    const float* x      = (const float*)d_in[0];
    const float* w_attn = (const float*)d_in[1];
    const float* b_attn = (const float*)d_in[2];
    const float* w_proj = (const float*)d_in[3];
    const float* b_proj = (const float*)d_in[4];
    float* out = (float*)d_out;

    // 1) QKV GEMM: [4096,1024] @ [1024,3072] + bias, scatter to [B,H,S,D]
    sgemm_kernel<<<dim3(3 * NX / 128, MTOK / 128), 256>>>(
        x, w_attn, b_attn, nullptr, MTOK, 3 * NX, NX, 1);

    // 2) Causal flash attention, 64-query tiles (static 48KB smem)
    attn_kernel<<<dim3(BB * HH, SS / 64), 256>>>();

    // 3) Projection: g_a [4096,1024] @ [1024,1024] + bias -> out
    sgemm_kernel<<<dim3(NX / 128, MTOK / 128), 256>>>(
        nullptr, w_proj, b_proj, out, MTOK, NX, NX, 0);
}

// round 7
// speedup vs baseline: 1.6021x; 1.6021x over previous
#include <cuda_runtime.h>
#include <cuda_bf16.h>
#include <cstdint>

// Problem constants (B=2, S=2048, NX=1024, H=16, D=64)
#define BB 2
#define SS 2048
#define NXC 1024
#define HH 16
#define DD 64
#define MTOK (BB*SS)   // 4096

// Scratch (device globals — no allocation allowed)
__device__ float g_q[(size_t)BB*HH*SS*DD];   // [B,H,S,D] 16 MB
__device__ float g_k[(size_t)BB*HH*SS*DD];
__device__ float g_v[(size_t)BB*HH*SS*DD];
__device__ float g_a[(size_t)BB*SS*NXC];     // merged-head attn out, 16 MB

// ---------------------------------------------------------------------------
// helpers
// ---------------------------------------------------------------------------
static __device__ __forceinline__ uint32_t f2tf(float f) {
    uint32_t r;
    asm("cvt.rna.tf32.f32 %0, %1;" : "=r"(r) : "f"(f));
    return r;
}
// m16n8k8 tf32 MMA: D += A*B (C==D accumulate in place)
static __device__ __forceinline__ void mma1688(float* c, const uint32_t* a,
                                               const uint32_t* b) {
    asm volatile(
        "mma.sync.aligned.m16n8k8.row.col.f32.tf32.tf32.f32 "
        "{%0,%1,%2,%3}, {%4,%5,%6,%7}, {%8,%9}, {%0,%1,%2,%3};"
        : "+f"(c[0]), "+f"(c[1]), "+f"(c[2]), "+f"(c[3])
        : "r"(a[0]), "r"(a[1]), "r"(a[2]), "r"(a[3]),
          "r"(b[0]), "r"(b[1]));
}

// ---------------------------------------------------------------------------
// tf32 tensor-core GEMM via mma.sync: C[128,128] tile = A[128,K] * B[K,N] tile
// 256 threads = 8 warps (4x2), warp tile 32x64 = 2x8 m16n8k8 fragments.
// BLK_K = 32. A is [M,K] row-major, B is [K,N] row-major (native w layout).
// mode 0: C[row*1024+col] = acc + bias[col]    (projection)
// mode 1: scatter to g_q/g_k/g_v [B,H,S,D]     (QKV; N = 3072)
// A == nullptr means "use g_a".
// ---------------------------------------------------------------------------
#define ASTR 36    // A smem row stride (floats): banks (r*4+c)&31 all distinct
#define BSTR 136   // B smem row stride: banks (k*8+n)&31 all distinct

__global__ __launch_bounds__(256)
void tc_gemm(const float* __restrict__ A, const float* __restrict__ Bm,
             const float* __restrict__ bias, float* __restrict__ C,
             int K, int N, int mode)
{
    __shared__ uint32_t As[128 * ASTR];   // [m][k]  18.4 KB
    __shared__ uint32_t Bs[32 * BSTR];    // [k][n]  17.4 KB

    const int tid = threadIdx.x;
    const int lane = tid & 31;
    const int warp = tid >> 5;
    const int warp_m = warp >> 1;          // 0..3
    const int warp_n = warp & 1;           // 0..1
    const int row0 = blockIdx.y * 128;
    const int col0 = blockIdx.x * 128;
    const float* Ap = A ? A : g_a;

    float acc[2][8][4];
#pragma unroll
    for (int mi = 0; mi < 2; mi++)
#pragma unroll
        for (int ni = 0; ni < 8; ni++)
#pragma unroll
            for (int e = 0; e < 4; e++) acc[mi][ni][e] = 0.f;

    const int lr = lane >> 2;   // 0..7
    const int lc = lane & 3;    // 0..3

    for (int k0 = 0; k0 < K; k0 += 32) {
        // Stage A tile 128x32 (f32 -> tf32), coalesced float4 along K
#pragma unroll
        for (int t = 0; t < 4; t++) {
            const int fid = tid + t * 256;       // 0..1023
            const int r = fid >> 3;              // 0..127
            const int c4 = (fid & 7) << 2;       // 0,4,...,28
            float4 v = *(const float4*)(Ap + (size_t)(row0 + r) * K + k0 + c4);
            *(uint4*)&As[r * ASTR + c4] =
                make_uint4(f2tf(v.x), f2tf(v.y), f2tf(v.z), f2tf(v.w));
        }
        // Stage B tile 32x128, coalesced float4 along N
#pragma unroll
        for (int t = 0; t < 4; t++) {
            const int fid = tid + t * 256;
            const int kk = fid >> 5;             // 0..31
            const int c4 = (fid & 31) << 2;      // 0..124
            float4 v = *(const float4*)(Bm + (size_t)(k0 + kk) * N + col0 + c4);
            *(uint4*)&Bs[kk * BSTR + c4] =
                make_uint4(f2tf(v.x), f2tf(v.y), f2tf(v.z), f2tf(v.w));
        }
        __syncthreads();

#pragma unroll
        for (int ks = 0; ks < 4; ks++) {
            // A fragments (2 m-tiles)
            uint32_t af[2][4];
#pragma unroll
            for (int mi = 0; mi < 2; mi++) {
                const int r = warp_m * 32 + mi * 16 + lr;
                const int c = ks * 8 + lc;
                af[mi][0] = As[r * ASTR + c];
                af[mi][1] = As[(r + 8) * ASTR + c];
                af[mi][2] = As[r * ASTR + c + 4];
                af[mi][3] = As[(r + 8) * ASTR + c + 4];
            }
            // B fragments (8 n-tiles)
            uint32_t bf[8][2];
#pragma unroll
            for (int ni = 0; ni < 8; ni++) {
                const int kk = ks * 8 + lc;
                const int n = warp_n * 64 + ni * 8 + lr;
                bf[ni][0] = Bs[kk * BSTR + n];
                bf[ni][1] = Bs[(kk + 4) * BSTR + n];
            }
#pragma unroll
            for (int mi = 0; mi < 2; mi++)
#pragma unroll
                for (int ni = 0; ni < 8; ni++)
                    mma1688(acc[mi][ni], af[mi], bf[ni]);
        }
        __syncthreads();
    }

    // Epilogue straight from C fragments.
    // c0:(r, c) c1:(r, c+1) c2:(r+8, c) c3:(r+8, c+1); r = base+lr, c = base+2*lc
#pragma unroll
    for (int mi = 0; mi < 2; mi++) {
#pragma unroll
        for (int ni = 0; ni < 8; ni++) {
            const int r = row0 + warp_m * 32 + mi * 16 + lr;
            const int c = col0 + warp_n * 64 + ni * 8 + 2 * lc;
#pragma unroll
            for (int e = 0; e < 4; e++) {
                const int row = r + (e >> 1) * 8;
                const int col = c + (e & 1);
                const float val = acc[mi][ni][e] + bias[col];
                if (mode == 0) {
                    C[(size_t)row * NXC + col] = val;
                } else {
                    const int bidx = row >> 11;     // /2048
                    const int s = row & 2047;
                    const int which = col >> 10;    // 0:q 1:k 2:v
                    const int hd = col & 1023;
                    const int h = hd >> 6;
                    const int d = hd & 63;
                    const size_t idx =
                        (((size_t)(bidx * HH + h)) * SS + s) * DD + d;
                    if (which == 0)      g_q[idx] = val;
                    else if (which == 1) g_k[idx] = val;
                    else                 g_v[idx] = val;
                }
            }
        }
    }
}

// ---------------------------------------------------------------------------
// Flash attention (unchanged from the passing round-4 kernel).
// One block = one (b,h) x 64-query tile, 256 threads, static 48KB smem.
// ---------------------------------------------------------------------------
__global__ __launch_bounds__(256, 2)
void attn_kernel()
{
    __shared__ float Qt[64 * 64];   // [d][r]
    __shared__ float KV[64 * 64];   // K as [d][c], then V as [c][d]
    __shared__ float Ps[64 * 64];   // [c][r]

    const int bh = blockIdx.x;
    const int qt = blockIdx.y;
    const int q0 = qt * 64;
    const int tid = threadIdx.x;
    const int tr = tid >> 4;
    const int tc = tid & 15;

    const float* Qg = g_q + (size_t)bh * SS * DD;
    const float* Kg = g_k + (size_t)bh * SS * DD;
    const float* Vg = g_v + (size_t)bh * SS * DD;

#pragma unroll
    for (int t = 0; t < 4; t++) {
        int fid = tid + t * 256;
        int r  = fid >> 4;
        int c4 = (fid & 15) << 2;
        float4 v = *(const float4*)(Qg + (size_t)(q0 + r) * DD + c4);
        Qt[(c4 + 0) * 64 + r] = v.x; Qt[(c4 + 1) * 64 + r] = v.y;
        Qt[(c4 + 2) * 64 + r] = v.z; Qt[(c4 + 3) * 64 + r] = v.w;
    }

    float m[4], l[4], o[4][4];
#pragma unroll
    for (int i = 0; i < 4; i++) {
        m[i] = -1e30f; l[i] = 0.f;
#pragma unroll
        for (int j = 0; j < 4; j++) o[i][j] = 0.f;
    }
    const float scale = 0.125f;

    for (int kt = 0; kt <= qt; kt++) {
        const int k0 = kt * 64;
        __syncthreads();
#pragma unroll
        for (int t = 0; t < 4; t++) {
            int fid = tid + t * 256;
            int r  = fid >> 4;
            int c4 = (fid & 15) << 2;
            float4 kv = *(const float4*)(Kg + (size_t)(k0 + r) * DD + c4);
            KV[(c4 + 0) * 64 + r] = kv.x; KV[(c4 + 1) * 64 + r] = kv.y;
            KV[(c4 + 2) * 64 + r] = kv.z; KV[(c4 + 3) * 64 + r] = kv.w;
        }
        __syncthreads();

        float s[4][4];
#pragma unroll
        for (int i = 0; i < 4; i++)
#pragma unroll
            for (int j = 0; j < 4; j++) s[i][j] = 0.f;
        for (int d = 0; d < 64; d++) {
            float4 a = *(float4*)&Qt[d * 64 + tr * 4];
            float4 b = *(float4*)&KV[d * 64 + tc * 4];
            float av[4] = {a.x, a.y, a.z, a.w};
            float bv[4] = {b.x, b.y, b.z, b.w};
#pragma unroll
            for (int i = 0; i < 4; i++)
#pragma unroll
                for (int j = 0; j < 4; j++)
                    s[i][j] = fmaf(av[i], bv[j], s[i][j]);
        }

        const bool diag = (kt == qt);
#pragma unroll
        for (int i = 0; i < 4; i++)
#pragma unroll
            for (int j = 0; j < 4; j++) {
                s[i][j] *= scale;
                if (diag && (k0 + tc * 4 + j) > (q0 + tr * 4 + i))
                    s[i][j] = -1e30f;
            }

        float alpha[4];
#pragma unroll
        for (int i = 0; i < 4; i++) {
            float mt = fmaxf(fmaxf(s[i][0], s[i][1]), fmaxf(s[i][2], s[i][3]));
#pragma unroll
            for (int off = 8; off > 0; off >>= 1)
                mt = fmaxf(mt, __shfl_xor_sync(0xffffffffu, mt, off));
            float mn = fmaxf(m[i], mt);
            alpha[i] = __expf(m[i] - mn);
            m[i] = mn;
            float sum = 0.f;
#pragma unroll
            for (int j = 0; j < 4; j++) {
                float p = __expf(s[i][j] - mn);
                s[i][j] = p;
                sum += p;
            }
#pragma unroll
            for (int off = 8; off > 0; off >>= 1)
                sum += __shfl_xor_sync(0xffffffffu, sum, off);
            l[i] = l[i] * alpha[i] + sum;
#pragma unroll
            for (int j = 0; j < 4; j++) o[i][j] *= alpha[i];
        }

#pragma unroll
        for (int j = 0; j < 4; j++)
            *(float4*)&Ps[(tc * 4 + j) * 64 + tr * 4] =
                make_float4(s[0][j], s[1][j], s[2][j], s[3][j]);
        __syncthreads();

#pragma unroll
        for (int t = 0; t < 4; t++) {
            int fid = tid + t * 256;
            int r  = fid >> 4;
            int c4 = (fid & 15) << 2;
            *(float4*)&KV[r * 64 + c4] =
                *(const float4*)(Vg + (size_t)(k0 + r) * DD + c4);
        }
        __syncthreads();

        for (int c = 0; c < 64; c++) {
            float4 a = *(float4*)&Ps[c * 64 + tr * 4];
            float4 b = *(float4*)&KV[c * 64 + tc * 4];
            float av[4] = {a.x, a.y, a.z, a.w};
            float bv[4] = {b.x, b.y, b.z, b.w};
#pragma unroll
            for (int i = 0; i < 4; i++)
#pragma unroll
                for (int j = 0; j < 4; j++)
                    o[i][j] = fmaf(av[i], bv[j], o[i][j]);
        }
    }

    const int b = bh >> 4;
    const int h = bh & 15;
#pragma unroll
    for (int i = 0; i < 4; i++) {
        float inv = 1.f / l[i];
        int srow = q0 + tr * 4 + i;
        float* dst = g_a + ((size_t)(b * SS + srow)) * NXC + h * DD + tc * 4;
        dst[0] = o[i][0] * inv;
        dst[1] = o[i][1] * inv;
        dst[2] = o[i][2] * inv;
        dst[3] = o[i][3] * inv;
    }
}

// ---------------------------------------------------------------------------
extern "C" void kernel_launch(void* const* d_in, const int* in_sizes, int n_in,
                              void* d_out, int out_size)
{
    const float* x      = (const float*)d_in[0];
    const float* w_attn = (const float*)d_in[1];
    const float* b_attn = (const float*)d_in[2];
    const float* w_proj = (const float*)d_in[3];
    const float* b_proj = (const float*)d_in[4];
    float* out = (float*)d_out;

    // 1) QKV GEMM (mma.sync tf32): [4096,1024] @ [1024,3072] -> scatter [B,H,S,D]
    tc_gemm<<<dim3(24, 32), 256>>>(x, w_attn, b_attn, nullptr, NXC, 3 * NXC, 1);

    // 2) Causal flash attention
    attn_kernel<<<dim3(BB * HH, SS / 64), 256>>>();

    // 3) Projection (mma.sync tf32): g_a @ [1024,1024] + bias -> out
    tc_gemm<<<dim3(8, 32), 256>>>(nullptr, w_proj, b_proj, out, NXC, NXC, 0);
}

// round 8
// speedup vs baseline: 3.3971x; 2.1204x over previous
#include <cuda_runtime.h>
#include <cuda_bf16.h>
#include <cstdint>

// Problem constants (B=2, S=2048, NX=1024, H=16, D=64)
#define BB 2
#define SS 2048
#define NXC 1024
#define HH 16
#define DD 64
#define MTOK (BB*SS)   // 4096

// Scratch (device globals — no allocation allowed)
__device__ float g_q[(size_t)BB*HH*SS*DD];   // [B,H,S,D]
__device__ float g_k[(size_t)BB*HH*SS*DD];   // [B,H,D,S]  (TRANSPOSED)
__device__ float g_v[(size_t)BB*HH*SS*DD];   // [B,H,S,D]
__device__ float g_a[(size_t)BB*SS*NXC];     // merged-head attn out

// ---------------------------------------------------------------------------
// helpers
// ---------------------------------------------------------------------------
static __device__ __forceinline__ uint32_t f2tf(float f) {
    uint32_t r;
    asm("cvt.rna.tf32.f32 %0, %1;" : "=r"(r) : "f"(f));
    return r;
}
// m16n8k8 tf32 MMA: D += A*B (C==D accumulate in place)
static __device__ __forceinline__ void mma1688(float* c, const uint32_t* a,
                                               const uint32_t* b) {
    asm volatile(
        "mma.sync.aligned.m16n8k8.row.col.f32.tf32.tf32.f32 "
        "{%0,%1,%2,%3}, {%4,%5,%6,%7}, {%8,%9}, {%0,%1,%2,%3};"
        : "+f"(c[0]), "+f"(c[1]), "+f"(c[2]), "+f"(c[3])
        : "r"(a[0]), "r"(a[1]), "r"(a[2]), "r"(a[3]),
          "r"(b[0]), "r"(b[1]));
}

// ---------------------------------------------------------------------------
// tf32 tensor-core GEMM via mma.sync (validated in round 7).
// mode 0: C[row*1024+col] = acc + bias[col]    (projection)
// mode 1: scatter q/v to [B,H,S,D], k to [B,H,D,S]   (QKV; N = 3072)
// ---------------------------------------------------------------------------
#define ASTR 36
#define BSTR 136

__global__ __launch_bounds__(256)
void tc_gemm(const float* __restrict__ A, const float* __restrict__ Bm,
             const float* __restrict__ bias, float* __restrict__ C,
             int K, int N, int mode)
{
    __shared__ uint32_t As[128 * ASTR];
    __shared__ uint32_t Bs[32 * BSTR];

    const int tid = threadIdx.x;
    const int lane = tid & 31;
    const int warp = tid >> 5;
    const int warp_m = warp >> 1;
    const int warp_n = warp & 1;
    const int row0 = blockIdx.y * 128;
    const int col0 = blockIdx.x * 128;
    const float* Ap = A ? A : g_a;

    float acc[2][8][4];
#pragma unroll
    for (int mi = 0; mi < 2; mi++)
#pragma unroll
        for (int ni = 0; ni < 8; ni++)
#pragma unroll
            for (int e = 0; e < 4; e++) acc[mi][ni][e] = 0.f;

    const int lr = lane >> 2;
    const int lc = lane & 3;

    for (int k0 = 0; k0 < K; k0 += 32) {
#pragma unroll
        for (int t = 0; t < 4; t++) {
            const int fid = tid + t * 256;
            const int r = fid >> 3;
            const int c4 = (fid & 7) << 2;
            float4 v = *(const float4*)(Ap + (size_t)(row0 + r) * K + k0 + c4);
            *(uint4*)&As[r * ASTR + c4] =
                make_uint4(f2tf(v.x), f2tf(v.y), f2tf(v.z), f2tf(v.w));
        }
#pragma unroll
        for (int t = 0; t < 4; t++) {
            const int fid = tid + t * 256;
            const int kk = fid >> 5;
            const int c4 = (fid & 31) << 2;
            float4 v = *(const float4*)(Bm + (size_t)(k0 + kk) * N + col0 + c4);
            *(uint4*)&Bs[kk * BSTR + c4] =
                make_uint4(f2tf(v.x), f2tf(v.y), f2tf(v.z), f2tf(v.w));
        }
        __syncthreads();

#pragma unroll
        for (int ks = 0; ks < 4; ks++) {
            uint32_t af[2][4];
#pragma unroll
            for (int mi = 0; mi < 2; mi++) {
                const int r = warp_m * 32 + mi * 16 + lr;
                const int c = ks * 8 + lc;
                af[mi][0] = As[r * ASTR + c];
                af[mi][1] = As[(r + 8) * ASTR + c];
                af[mi][2] = As[r * ASTR + c + 4];
                af[mi][3] = As[(r + 8) * ASTR + c + 4];
            }
            uint32_t bf[8][2];
#pragma unroll
            for (int ni = 0; ni < 8; ni++) {
                const int kk = ks * 8 + lc;
                const int n = warp_n * 64 + ni * 8 + lr;
                bf[ni][0] = Bs[kk * BSTR + n];
                bf[ni][1] = Bs[(kk + 4) * BSTR + n];
            }
#pragma unroll
            for (int mi = 0; mi < 2; mi++)
#pragma unroll
                for (int ni = 0; ni < 8; ni++)
                    mma1688(acc[mi][ni], af[mi], bf[ni]);
        }
        __syncthreads();
    }

#pragma unroll
    for (int mi = 0; mi < 2; mi++) {
#pragma unroll
        for (int ni = 0; ni < 8; ni++) {
            const int r = row0 + warp_m * 32 + mi * 16 + lr;
            const int c = col0 + warp_n * 64 + ni * 8 + 2 * lc;
#pragma unroll
            for (int e = 0; e < 4; e++) {
                const int row = r + (e >> 1) * 8;
                const int col = c + (e & 1);
                const float val = acc[mi][ni][e] + bias[col];
                if (mode == 0) {
                    C[(size_t)row * NXC + col] = val;
                } else {
                    const int bidx = row >> 11;
                    const int s = row & 2047;
                    const int which = col >> 10;
                    const int hd = col & 1023;
                    const int h = hd >> 6;
                    const int d = hd & 63;
                    if (which == 0) {
                        g_q[(((size_t)(bidx * HH + h)) * SS + s) * DD + d] = val;
                    } else if (which == 1) {
                        // K transposed: [B,H,D,S]
                        g_k[(((size_t)(bidx * HH + h)) * DD + d) * SS + s] = val;
                    } else {
                        g_v[(((size_t)(bidx * HH + h)) * SS + s) * DD + d] = val;
                    }
                }
            }
        }
    }
}

// ---------------------------------------------------------------------------
// Tensor-core flash attention.
// One block = one (b,h) x 128-query tile, 256 threads = 8 warps.
// Warp w owns query rows [w*16, w*16+16); full 64-key width per KV tile.
// S = Q K^T and O += P V both via m16n8k8 tf32.
//   Qs [128][68]  A for S          (banks 4*lr+lc conflict-free)
//   Ps [128][68]  A for O (warp-private rows, no block sync needed)
//   Ks [64][72]   B for S, layout [d][key]  (g_k is pre-transposed)
//   Vs [64][72]   B for O, layout [c][d]    (natural)
// ---------------------------------------------------------------------------
#define QSTR 68
#define KSTR 72
#define ATTN_SMEM ((2*128*QSTR + 2*64*KSTR) * 4)   // 106496 bytes

__global__ __launch_bounds__(256)
void attn_mma_kernel()
{
    extern __shared__ uint32_t smem[];
    uint32_t* Qs = smem;                      // 128*68
    uint32_t* Ps = Qs + 128 * QSTR;           // 128*68
    uint32_t* Ks = Ps + 128 * QSTR;           // 64*72
    uint32_t* Vs = Ks + 64 * KSTR;            // 64*72

    const int bh = blockIdx.x;                // b*16+h
    const int qt = blockIdx.y;                // 0..15
    const int q0 = qt * 128;
    const int tid = threadIdx.x;
    const int lane = tid & 31;
    const int warp = tid >> 5;
    const int lr = lane >> 2;                 // 0..7
    const int lc = lane & 3;                  // 0..3
    const int wr = warp * 16;                 // warp base row

    const float* Qg  = g_q + (size_t)bh * SS * DD;    // [s][d]
    const float* KgT = g_k + (size_t)bh * DD * SS;    // [d][s]
    const float* Vg  = g_v + (size_t)bh * SS * DD;    // [s][d]

    // Stage Q tile [128][64] as tf32
#pragma unroll
    for (int t = 0; t < 8; t++) {
        const int fid = tid + t * 256;
        const int r = fid >> 4;                // 0..127
        const int c4 = (fid & 15) << 2;        // 0..60
        float4 v = *(const float4*)(Qg + (size_t)(q0 + r) * DD + c4);
        *(uint4*)&Qs[r * QSTR + c4] =
            make_uint4(f2tf(v.x), f2tf(v.y), f2tf(v.z), f2tf(v.w));
    }

    float oacc[8][4];
#pragma unroll
    for (int ni = 0; ni < 8; ni++)
#pragma unroll
        for (int e = 0; e < 4; e++) oacc[ni][e] = 0.f;
    float m0 = -1e30f, m1 = -1e30f, l0 = 0.f, l1 = 0.f;
    const float scale = 0.125f;               // 1/sqrt(64)

    const int nkt = 2 * qt + 2;
    for (int kt = 0; kt < nkt; kt++) {
        const int k0 = kt * 64;

        __syncthreads();   // prev O-mma done (Vs/Ks free); Qs ready on iter 0
        // Stage K^T [d][key] and V [c][d]
#pragma unroll
        for (int t = 0; t < 4; t++) {
            const int fid = tid + t * 256;
            const int r = fid >> 4;            // 0..63
            const int c4 = (fid & 15) << 2;    // 0..60
            float4 kv = *(const float4*)(KgT + (size_t)r * SS + k0 + c4);
            *(uint4*)&Ks[r * KSTR + c4] =
                make_uint4(f2tf(kv.x), f2tf(kv.y), f2tf(kv.z), f2tf(kv.w));
            float4 vv = *(const float4*)(Vg + (size_t)(k0 + r) * DD + c4);
            *(uint4*)&Vs[r * KSTR + c4] =
                make_uint4(f2tf(vv.x), f2tf(vv.y), f2tf(vv.z), f2tf(vv.w));
        }
        __syncthreads();

        // S = Q K^T : warp tile 16 x 64 (8 n-tiles), k = 64 (8 steps)
        float sacc[8][4];
#pragma unroll
        for (int ni = 0; ni < 8; ni++)
#pragma unroll
            for (int e = 0; e < 4; e++) sacc[ni][e] = 0.f;
#pragma unroll
        for (int ks = 0; ks < 8; ks++) {
            uint32_t af[4];
            const int c = ks * 8 + lc;
            af[0] = Qs[(wr + lr) * QSTR + c];
            af[1] = Qs[(wr + lr + 8) * QSTR + c];
            af[2] = Qs[(wr + lr) * QSTR + c + 4];
            af[3] = Qs[(wr + lr + 8) * QSTR + c + 4];
#pragma unroll
            for (int ni = 0; ni < 8; ni++) {
                uint32_t bf[2];
                const int n = ni * 8 + lr;
                bf[0] = Ks[c * KSTR + n];
                bf[1] = Ks[(c + 4) * KSTR + n];
                mma1688(sacc[ni], af, bf);
            }
        }

        // scale + causal mask (only the last two tiles intersect the diagonal)
        const bool need_mask = (k0 + 63 > q0);
        const int r0g = q0 + wr + lr;
        const int r1g = r0g + 8;
#pragma unroll
        for (int ni = 0; ni < 8; ni++) {
            const int c0g = k0 + ni * 8 + 2 * lc;
#pragma unroll
            for (int e = 0; e < 4; e++) sacc[ni][e] *= scale;
            if (need_mask) {
                if (c0g     > r0g) sacc[ni][0] = -1e30f;
                if (c0g + 1 > r0g) sacc[ni][1] = -1e30f;
                if (c0g     > r1g) sacc[ni][2] = -1e30f;
                if (c0g + 1 > r1g) sacc[ni][3] = -1e30f;
            }
        }

        // online softmax: rows lr (e0,e1) and lr+8 (e2,e3); quad = lanes lc
        float mx0 = -1e30f, mx1 = -1e30f;
#pragma unroll
        for (int ni = 0; ni < 8; ni++) {
            mx0 = fmaxf(mx0, fmaxf(sacc[ni][0], sacc[ni][1]));
            mx1 = fmaxf(mx1, fmaxf(sacc[ni][2], sacc[ni][3]));
        }
        mx0 = fmaxf(mx0, __shfl_xor_sync(0xffffffffu, mx0, 1));
        mx0 = fmaxf(mx0, __shfl_xor_sync(0xffffffffu, mx0, 2));
        mx1 = fmaxf(mx1, __shfl_xor_sync(0xffffffffu, mx1, 1));
        mx1 = fmaxf(mx1, __shfl_xor_sync(0xffffffffu, mx1, 2));

        const float mn0 = fmaxf(m0, mx0);
        const float mn1 = fmaxf(m1, mx1);
        const float a0 = __expf(m0 - mn0);
        const float a1 = __expf(m1 - mn1);
        m0 = mn0; m1 = mn1;

        float sum0 = 0.f, sum1 = 0.f;
#pragma unroll
        for (int ni = 0; ni < 8; ni++) {
            const float p0 = __expf(sacc[ni][0] - mn0);
            const float p1 = __expf(sacc[ni][1] - mn0);
            const float p2 = __expf(sacc[ni][2] - mn1);
            const float p3 = __expf(sacc[ni][3] - mn1);
            sum0 += p0 + p1;
            sum1 += p2 + p3;
            const int co = ni * 8 + 2 * lc;
            *(uint2*)&Ps[(wr + lr) * QSTR + co]     = make_uint2(f2tf(p0), f2tf(p1));
            *(uint2*)&Ps[(wr + lr + 8) * QSTR + co] = make_uint2(f2tf(p2), f2tf(p3));
        }
        sum0 += __shfl_xor_sync(0xffffffffu, sum0, 1);
        sum0 += __shfl_xor_sync(0xffffffffu, sum0, 2);
        sum1 += __shfl_xor_sync(0xffffffffu, sum1, 1);
        sum1 += __shfl_xor_sync(0xffffffffu, sum1, 2);
        l0 = l0 * a0 + sum0;
        l1 = l1 * a1 + sum1;

#pragma unroll
        for (int ni = 0; ni < 8; ni++) {
            oacc[ni][0] *= a0; oacc[ni][1] *= a0;
            oacc[ni][2] *= a1; oacc[ni][3] *= a1;
        }
        __syncwarp();   // P rows are warp-private; order STS -> LDS in-warp

        // O += P V : k = 64 keys (8 steps), 8 d-tiles
#pragma unroll
        for (int ks = 0; ks < 8; ks++) {
            uint32_t af[4];
            const int c = ks * 8 + lc;
            af[0] = Ps[(wr + lr) * QSTR + c];
            af[1] = Ps[(wr + lr + 8) * QSTR + c];
            af[2] = Ps[(wr + lr) * QSTR + c + 4];
            af[3] = Ps[(wr + lr + 8) * QSTR + c + 4];
#pragma unroll
            for (int ni = 0; ni < 8; ni++) {
                uint32_t bf[2];
                const int n = ni * 8 + lr;
                bf[0] = Vs[c * KSTR + n];
                bf[1] = Vs[(c + 4) * KSTR + n];
                mma1688(oacc[ni], af, bf);
            }
        }
    }

    // Normalize + write to g_a[b][s][h*64+d]
    const int b = bh >> 4;
    const int h = bh & 15;
    const float inv0 = 1.f / l0;
    const float inv1 = 1.f / l1;
    const int r0g = q0 + wr + lr;
#pragma unroll
    for (int ni = 0; ni < 8; ni++) {
        const int col = h * DD + ni * 8 + 2 * lc;
        float* d0 = g_a + ((size_t)(b * SS + r0g)) * NXC + col;
        float* d1 = g_a + ((size_t)(b * SS + r0g + 8)) * NXC + col;
        *(float2*)d0 = make_float2(oacc[ni][0] * inv0, oacc[ni][1] * inv0);
        *(float2*)d1 = make_float2(oacc[ni][2] * inv1, oacc[ni][3] * inv1);
    }
}

// ---------------------------------------------------------------------------
extern "C" void kernel_launch(void* const* d_in, const int* in_sizes, int n_in,
                              void* d_out, int out_size)
{
    const float* x      = (const float*)d_in[0];
    const float* w_attn = (const float*)d_in[1];
    const float* b_attn = (const float*)d_in[2];
    const float* w_proj = (const float*)d_in[3];
    const float* b_proj = (const float*)d_in[4];
    float* out = (float*)d_out;

    // Opt-in for >48KB dynamic smem (idempotent host API; not a stream op)
    cudaFuncSetAttribute(attn_mma_kernel,
                         cudaFuncAttributeMaxDynamicSharedMemorySize, ATTN_SMEM);

    // 1) QKV GEMM (mma.sync tf32); K written transposed [B,H,D,S]
    tc_gemm<<<dim3(24, 32), 256>>>(x, w_attn, b_attn, nullptr, NXC, 3 * NXC, 1);

    // 2) Tensor-core causal flash attention, 128-query tiles
    attn_mma_kernel<<<dim3(BB * HH, SS / 128), 256, ATTN_SMEM>>>();

    // 3) Projection (mma.sync tf32)
    tc_gemm<<<dim3(8, 32), 256>>>(nullptr, w_proj, b_proj, out, NXC, NXC, 0);
}